// round 4
// baseline (speedup 1.0000x reference)
#include <cuda_runtime.h>

// Problem constants: B=4, N=1024, C=256, H=8
#define Cc 256
#define Hh 8
#define KA 2048      // C*H, contraction length for W fold
#define KSPLIT 32    // split-K factor for kernel A (deterministic, no atomics)

typedef unsigned long long u64;

// Scratch (no allocation allowed -> __device__ globals)
__device__ float g_partial[KSPLIT * Cc * Cc];  // 8 MB split-K partials
__device__ float g_W[Cc * Cc];                 // folded matrix W[j'][j]
__device__ float g_c[Cc];                      // folded bias vector

// ---- f32x2 packed helpers (FFMA2 path: PTX-only, 2x FFMA throughput) ----
__device__ __forceinline__ u64 pack2(float x, float y) {
    u64 r; asm("mov.b64 %0, {%1,%2};" : "=l"(r) : "f"(x), "f"(y)); return r;
}
__device__ __forceinline__ void fma2(u64& d, u64 a, u64 b) {
    asm("fma.rn.f32x2 %0, %1, %2, %0;" : "+l"(d) : "l"(a), "l"(b));
}
__device__ __forceinline__ float2 unpack2(u64 v) {
    float2 r; asm("mov.b64 {%0,%1}, %2;" : "=f"(r.x), "=f"(r.y) : "l"(v)); return r;
}

// ---------------------------------------------------------------------------
// Kernel A: partial_z[j'][j] = sum_{k in z-th 64-chunk} Vr[k][j'] * lin[k][j]
//   k = i*H + h ; Vr[k][j'] = V[i*C*H + j'*H + h] ; lin row index == k.
//   Tile 128(j') x 64(j), 256 threads, micro 8x4 (j' packed in f32x2 pairs).
//   Grid (4 j-tiles, 2 j'-tiles, 32 z). Two 32-k sub-chunks per block.
// ---------------------------------------------------------------------------
__global__ __launch_bounds__(256) void kA(const float* __restrict__ V,
                                          const float* __restrict__ lin) {
    __shared__ float As[32][130];  // [k][j'] stride 130: u64-aligned, 2-way store
    __shared__ u64   Bd[32][66];   // [k][j] value duplicated in both f32x2 lanes

    const int t  = threadIdx.x;
    const int tx = t & 15;         // j  micro coord (x4)
    const int ty = t >> 4;         // j' micro coord (x8 = 4 pairs)
    const int j0  = blockIdx.x * 64;
    const int jp0 = blockIdx.y * 128;
    const int z   = blockIdx.z;

    u64 acc[4][4] = {};            // [j'-pair][j]

    for (int kc = 0; kc < 64; kc += 32) {
        __syncthreads();
        // As: for 4 i's, V[i, jp0:jp0+128, 0:8] is 1024 CONTIGUOUS floats
        // (j' stride 8, h stride 1). k-local = il*8 + h.
        #pragma unroll
        for (int il = 0; il < 4; ++il) {
            const float* chunk = V + (z * 8 + (kc >> 3) + il) * (Cc * Hh) + jp0 * Hh;
            #pragma unroll
            for (int q = 0; q < 4; ++q) {
                int idx = t + q * 256;
                As[il * 8 + (idx & 7)][idx >> 3] = chunk[idx];
            }
        }
        // Bd: lin rows z*64+kc .. +31, cols j0..j0+63, duplicated-packed
        #pragma unroll
        for (int it = 0; it < 2; ++it) {
            int r  = (t >> 4) + it * 16;
            int c4 = (t & 15) * 4;
            float4 w = *(const float4*)&lin[(z * 64 + kc + r) * Cc + j0 + c4];
            Bd[r][c4 + 0] = pack2(w.x, w.x);
            Bd[r][c4 + 1] = pack2(w.y, w.y);
            Bd[r][c4 + 2] = pack2(w.z, w.z);
            Bd[r][c4 + 3] = pack2(w.w, w.w);
        }
        __syncthreads();

        #pragma unroll 4
        for (int k = 0; k < 32; ++k) {
            u64 a[4], b[4];
            #pragma unroll
            for (int e = 0; e < 4; ++e) a[e] = *(const u64*)&As[k][ty * 8 + 2 * e];
            #pragma unroll
            for (int e = 0; e < 4; ++e) b[e] = Bd[k][tx * 4 + e];
            #pragma unroll
            for (int e1 = 0; e1 < 4; ++e1)
                #pragma unroll
                for (int e2 = 0; e2 < 4; ++e2)
                    fma2(acc[e1][e2], a[e1], b[e2]);
        }
    }

    #pragma unroll
    for (int e1 = 0; e1 < 4; ++e1) {
        float2 p0 = unpack2(acc[e1][0]);
        float2 p1 = unpack2(acc[e1][1]);
        float2 p2 = unpack2(acc[e1][2]);
        float2 p3 = unpack2(acc[e1][3]);
        int jp = jp0 + ty * 8 + 2 * e1;
        *(float4*)&g_partial[(z * Cc + jp) * Cc + j0 + tx * 4] =
            make_float4(p0.x, p1.x, p2.x, p3.x);
        *(float4*)&g_partial[(z * Cc + jp + 1) * Cc + j0 + tx * 4] =
            make_float4(p0.y, p1.y, p2.y, p3.y);
    }
}

// ---------------------------------------------------------------------------
// Kernel R: reduce split-K partials into g_W; block 256 computes g_c.
// ---------------------------------------------------------------------------
__global__ __launch_bounds__(256) void kR(const float* __restrict__ lin,
                                          const float* __restrict__ biasV) {
    if (blockIdx.x < 256) {
        int idx = blockIdx.x * 256 + threadIdx.x;
        float s = 0.0f;
        #pragma unroll
        for (int z = 0; z < KSPLIT; ++z)
            s += g_partial[z * (Cc * Cc) + idx];
        g_W[idx] = s;
    } else {
        // c[j] = sum_k biasV[k] * lin[k*C + j]  (biasV flat index i*H+h == k)
        int j = threadIdx.x;
        float s0 = 0.f, s1 = 0.f, s2 = 0.f, s3 = 0.f;
        for (int k = 0; k < KA; k += 4) {
            s0 = fmaf(biasV[k + 0], lin[(k + 0) * Cc + j], s0);
            s1 = fmaf(biasV[k + 1], lin[(k + 1) * Cc + j], s1);
            s2 = fmaf(biasV[k + 2], lin[(k + 2) * Cc + j], s2);
            s3 = fmaf(biasV[k + 3], lin[(k + 3) * Cc + j], s3);
        }
        g_c[j] = (s0 + s1) + (s2 + s3);
    }
}

// ---------------------------------------------------------------------------
// Kernel B: out[m][j] = sum_{j'} v[m][j'] * W[j'][j] + c[j]
//   M = 4096, Nout = 256, K = 256. Tile 128(m) x 64(j), 256 threads,
//   micro 8x4 (m packed in f32x2 pairs). Grid (4 j-tiles, 32 m-tiles) = 128.
//   v staged TRANSPOSED (VsT[k][m]) so compute reads are conflict-free rows.
// ---------------------------------------------------------------------------
__global__ __launch_bounds__(256) void kB(const float* __restrict__ v,
                                          float* __restrict__ out) {
    __shared__ float VsT[32][130];  // [k][m] stride 130
    __shared__ u64   Wd[32][66];    // [k][j] duplicated-packed

    const int t  = threadIdx.x;
    const int tx = t & 15;          // j micro coord (x4)
    const int ty = t >> 4;          // m micro coord (x8 = 4 pairs)
    const int j0 = blockIdx.x * 64;
    const int m0 = blockIdx.y * 128;

    u64 acc[4][4] = {};             // [m-pair][j]

    for (int ks = 0; ks < Cc; ks += 32) {
        __syncthreads();
        // VsT: v rows m0..m0+127, cols ks..ks+31, transposed at store.
        #pragma unroll
        for (int it = 0; it < 4; ++it) {
            int r  = (t >> 3) + it * 32;   // m row 0..127
            int c4 = (t & 7) * 4;          // k col 0..28
            float4 val = *(const float4*)&v[(m0 + r) * Cc + ks + c4];
            VsT[c4 + 0][r] = val.x;
            VsT[c4 + 1][r] = val.y;
            VsT[c4 + 2][r] = val.z;
            VsT[c4 + 3][r] = val.w;
        }
        // Wd: g_W rows ks..ks+31, cols j0..j0+63, duplicated-packed
        #pragma unroll
        for (int it = 0; it < 2; ++it) {
            int r  = (t >> 4) + it * 16;
            int c4 = (t & 15) * 4;
            float4 w = *(const float4*)&g_W[(ks + r) * Cc + j0 + c4];
            Wd[r][c4 + 0] = pack2(w.x, w.x);
            Wd[r][c4 + 1] = pack2(w.y, w.y);
            Wd[r][c4 + 2] = pack2(w.z, w.z);
            Wd[r][c4 + 3] = pack2(w.w, w.w);
        }
        __syncthreads();

        #pragma unroll 4
        for (int kk = 0; kk < 32; ++kk) {
            u64 a[4], b[4];
            #pragma unroll
            for (int e = 0; e < 4; ++e) a[e] = *(const u64*)&VsT[kk][ty * 8 + 2 * e];
            #pragma unroll
            for (int e = 0; e < 4; ++e) b[e] = Wd[kk][tx * 4 + e];
            #pragma unroll
            for (int e1 = 0; e1 < 4; ++e1)
                #pragma unroll
                for (int e2 = 0; e2 < 4; ++e2)
                    fma2(acc[e1][e2], a[e1], b[e2]);
        }
    }

    float4 cv = *(const float4*)&g_c[j0 + tx * 4];
    #pragma unroll
    for (int e1 = 0; e1 < 4; ++e1) {
        float2 p0 = unpack2(acc[e1][0]);
        float2 p1 = unpack2(acc[e1][1]);
        float2 p2 = unpack2(acc[e1][2]);
        float2 p3 = unpack2(acc[e1][3]);
        int m = m0 + ty * 8 + 2 * e1;
        *(float4*)&out[m * Cc + j0 + tx * 4] =
            make_float4(p0.x + cv.x, p1.x + cv.y, p2.x + cv.z, p3.x + cv.w);
        *(float4*)&out[(m + 1) * Cc + j0 + tx * 4] =
            make_float4(p0.y + cv.x, p1.y + cv.y, p2.y + cv.z, p3.y + cv.w);
    }
}

// ---------------------------------------------------------------------------
// Inputs (metadata order): q, k, v, bias, atten_mask, Q, K, V,
//                          bias_Q, bias_K, bias_V, linear_output
// Only v (d_in[2]), V (d_in[7]), bias_V (d_in[10]), linear_output (d_in[11])
// matter: softmax over m sums to 1, so the attention block is the identity
// on vh; everything folds to out = v @ (Vr^T @ lin) + c.
// ---------------------------------------------------------------------------
extern "C" void kernel_launch(void* const* d_in, const int* in_sizes, int n_in,
                              void* d_out, int out_size) {
    const float* v     = (const float*)d_in[2];
    const float* V     = (const float*)d_in[7];
    const float* biasV = (const float*)d_in[10];
    const float* lin   = (const float*)d_in[11];
    float* out = (float*)d_out;

    kA<<<dim3(4, 2, KSPLIT), 256>>>(V, lin);
    kR<<<257, 256>>>(lin, biasV);
    kB<<<dim3(4, 32), 256>>>(v, out);
}

// round 5
// speedup vs baseline: 1.1526x; 1.1526x over previous
#include <cuda_runtime.h>

// Problem constants: B=4, N=1024, C=256, H=8
#define Cc 256
#define Hh 8
#define KA 2048      // C*H, contraction length for W fold
#define KSPLIT 32    // split-K factor for kernel A (deterministic, no atomics)

// Scratch (no allocation allowed -> __device__ globals)
__device__ float g_partial[KSPLIT * Cc * Cc];  // 8 MB split-K partials
__device__ float g_W[Cc * Cc];                 // folded matrix W[j'][j]
__device__ float g_c[Cc];                      // folded bias vector

// ---------------------------------------------------------------------------
// Kernel A: partial_z[j'][j] = sum_{k in z-th 64-chunk} Vr[k][j'] * lin[k][j]
//   k = i*H + h ; Vr[k][j'] = V[i*C*H + j'*H + h] ; lin row index == k.
//   Block: 64x64 output tile, 256 threads, 4x4 micro-tile.
//   Grid: (4 j-tiles, 4 j'-tiles, 32 k-splits); each split = 8 i's = 64 k.
//   ONE sync pair per block; compute = 1024 straight-line FMAs/thread.
//   (Identical to the measured-12.3us round-3 version.)
// ---------------------------------------------------------------------------
__global__ __launch_bounds__(256) void kA(const float* __restrict__ V,
                                          const float* __restrict__ lin) {
    __shared__ float As[64][68];   // [k-local][j'-local]
    __shared__ float Bs[64][68];   // [k-local][j-local]

    const int t  = threadIdx.x;
    const int tx = t & 15;         // j  micro coord
    const int ty = t >> 4;         // j' micro coord
    const int j0  = blockIdx.x * 64;
    const int jp0 = blockIdx.y * 64;
    const int z   = blockIdx.z;

    // As: for each of 8 i's, V[i, jp0:jp0+64, 0:8] is 512 CONTIGUOUS floats
    // (j' stride 8, h stride 1). k-local = i_local*8 + h.
    #pragma unroll
    for (int il = 0; il < 8; ++il) {
        const float* chunk = V + (z * 8 + il) * (Cc * Hh) + jp0 * Hh;
        float v0 = chunk[t];
        float v1 = chunk[t + 256];
        As[il * 8 + (t & 7)][t >> 3]        = v0;
        As[il * 8 + (t & 7)][(t >> 3) + 32] = v1;
    }
    // Bs: lin rows z*64 .. z*64+63, cols j0..j0+63
    #pragma unroll
    for (int it = 0; it < 4; ++it) {
        int r  = (t >> 4) + it * 16;
        int c4 = (t & 15) * 4;
        *(float4*)&Bs[r][c4] = *(const float4*)&lin[(z * 64 + r) * Cc + j0 + c4];
    }
    __syncthreads();

    float acc[4][4] = {};
    #pragma unroll 16
    for (int k = 0; k < 64; ++k) {
        float4 a4 = *(const float4*)&As[k][ty * 4];
        float4 b4 = *(const float4*)&Bs[k][tx * 4];
        float a[4] = {a4.x, a4.y, a4.z, a4.w};
        float b[4] = {b4.x, b4.y, b4.z, b4.w};
        #pragma unroll
        for (int e1 = 0; e1 < 4; ++e1)
            #pragma unroll
            for (int e2 = 0; e2 < 4; ++e2)
                acc[e1][e2] = fmaf(a[e1], b[e2], acc[e1][e2]);
    }

    #pragma unroll
    for (int e1 = 0; e1 < 4; ++e1) {
        int jp = jp0 + ty * 4 + e1;
        float4 val = make_float4(acc[e1][0], acc[e1][1], acc[e1][2], acc[e1][3]);
        *(float4*)&g_partial[(z * Cc + jp) * Cc + j0 + tx * 4] = val;
    }
}

// ---------------------------------------------------------------------------
// Kernel R: reduce split-K partials into g_W; block 256 computes g_c.
// ---------------------------------------------------------------------------
__global__ __launch_bounds__(256) void kR(const float* __restrict__ lin,
                                          const float* __restrict__ biasV) {
    if (blockIdx.x < 256) {
        int idx = blockIdx.x * 256 + threadIdx.x;
        float s = 0.0f;
        #pragma unroll
        for (int z = 0; z < KSPLIT; ++z)
            s += g_partial[z * (Cc * Cc) + idx];
        g_W[idx] = s;
    } else {
        // c[j] = sum_k biasV[k] * lin[k*C + j]  (biasV flat index i*H+h == k)
        int j = threadIdx.x;
        float s0 = 0.f, s1 = 0.f, s2 = 0.f, s3 = 0.f;
        for (int k = 0; k < KA; k += 4) {
            s0 = fmaf(biasV[k + 0], lin[(k + 0) * Cc + j], s0);
            s1 = fmaf(biasV[k + 1], lin[(k + 1) * Cc + j], s1);
            s2 = fmaf(biasV[k + 2], lin[(k + 2) * Cc + j], s2);
            s3 = fmaf(biasV[k + 3], lin[(k + 3) * Cc + j], s3);
        }
        g_c[j] = (s0 + s1) + (s2 + s3);
    }
}

// ---------------------------------------------------------------------------
// Kernel B: out[m][j] = sum_{j'} v[m][j'] * W[j'][j] + c[j]
//   M = B*N = 4096, Nout = 256, K = 256.
//   Block: 64(m) x 64(j) tile, 256 threads, 4x4 micro. Grid (4, 64).
//   K staged in 64-wide chunks. v staged TRANSPOSED: VsT[k][m] (stride 65)
//   so the compute a-read VsT[kk][ty*4+e] is a 16-lane broadcast
//   (address depends only on ty) -> conflict-free, unlike the stride-68
//   column read of round 3 which was 8-way conflicted.
// ---------------------------------------------------------------------------
__global__ __launch_bounds__(256) void kB(const float* __restrict__ v,
                                          float* __restrict__ out) {
    __shared__ float VsT[64][65]; // [k-local][m-local]
    __shared__ float Ws[64][68];  // [k-local][j-local]

    const int t  = threadIdx.x;
    const int tx = t & 15;        // j micro coord
    const int ty = t >> 4;        // m micro coord
    const int j0 = blockIdx.x * 64;
    const int m0 = blockIdx.y * 64;

    float acc[4][4] = {};

    for (int ks = 0; ks < Cc; ks += 64) {
        __syncthreads();  // previous chunk fully consumed
        // VsT: v rows m0..m0+63, k cols ks..ks+63, transposed at store.
        #pragma unroll
        for (int it = 0; it < 4; ++it) {
            int r  = (t >> 4) + it * 16;   // m row 0..63
            int c4 = (t & 15) * 4;         // k col 0..60
            float4 val = *(const float4*)&v[(m0 + r) * Cc + ks + c4];
            VsT[c4 + 0][r] = val.x;
            VsT[c4 + 1][r] = val.y;
            VsT[c4 + 2][r] = val.z;
            VsT[c4 + 3][r] = val.w;
        }
        #pragma unroll
        for (int it = 0; it < 4; ++it) {
            int r  = (t >> 4) + it * 16;   // k row
            int c4 = (t & 15) * 4;         // j col
            *(float4*)&Ws[r][c4] = *(const float4*)&g_W[(ks + r) * Cc + j0 + c4];
        }
        __syncthreads();

        #pragma unroll 16
        for (int kk = 0; kk < 64; ++kk) {
            float a[4];
            #pragma unroll
            for (int e = 0; e < 4; ++e) a[e] = VsT[kk][ty * 4 + e];
            float4 b4 = *(const float4*)&Ws[kk][tx * 4];
            float b[4] = {b4.x, b4.y, b4.z, b4.w};
            #pragma unroll
            for (int e1 = 0; e1 < 4; ++e1)
                #pragma unroll
                for (int e2 = 0; e2 < 4; ++e2)
                    acc[e1][e2] = fmaf(a[e1], b[e2], acc[e1][e2]);
        }
    }

    float4 cv = *(const float4*)&g_c[j0 + tx * 4];
    #pragma unroll
    for (int e1 = 0; e1 < 4; ++e1) {
        int m = m0 + ty * 4 + e1;
        float4 val = make_float4(acc[e1][0] + cv.x, acc[e1][1] + cv.y,
                                 acc[e1][2] + cv.z, acc[e1][3] + cv.w);
        *(float4*)&out[m * Cc + j0 + tx * 4] = val;
    }
}

// ---------------------------------------------------------------------------
// Inputs (metadata order): q, k, v, bias, atten_mask, Q, K, V,
//                          bias_Q, bias_K, bias_V, linear_output
// Only v (d_in[2]), V (d_in[7]), bias_V (d_in[10]), linear_output (d_in[11])
// matter: softmax over m sums to 1, so the attention block is the identity
// on vh; everything folds to out = v @ (Vr^T @ lin) + c.
// ---------------------------------------------------------------------------
extern "C" void kernel_launch(void* const* d_in, const int* in_sizes, int n_in,
                              void* d_out, int out_size) {
    const float* v     = (const float*)d_in[2];
    const float* V     = (const float*)d_in[7];
    const float* biasV = (const float*)d_in[10];
    const float* lin   = (const float*)d_in[11];
    float* out = (float*)d_out;

    kA<<<dim3(4, 4, KSPLIT), 256>>>(V, lin);
    kR<<<257, 256>>>(lin, biasV);
    kB<<<dim3(4, 64), 256>>>(v, out);
}

// round 6
// speedup vs baseline: 2.5433x; 2.2065x over previous
#include <cuda_runtime.h>

// Problem constants: B=4, N=1024, C=256, H=8
#define Cc 256
#define Hh 8
#define KA 2048      // C*H, contraction length for W fold
#define KSPLIT 32    // split-K factor for kernel A (deterministic, no atomics)

// Scratch (no allocation allowed -> __device__ globals)
__device__ float g_partial[KSPLIT * Cc * Cc];  // 8 MB split-K partials
__device__ float g_W[Cc * Cc];                 // folded matrix W[j'][j]
__device__ float g_cp[KSPLIT * Cc];            // c partials per k-split
__device__ float g_c[Cc];                      // folded bias vector

// ---------------------------------------------------------------------------
// Kernel A: partial_z[j'][j] = sum_{k in z-th 64-chunk} Vr[k][j'] * lin[k][j]
//   k = i*H + h ; Vr[k][j'] = V[i*C*H + j'*H + h] ; lin row index == k.
//   Block: 64x64 output tile, 256 threads, 4x4 micro-tile.
//   Grid: (4 j-tiles, 4 j'-tiles, 32 k-splits); each split = 8 i's = 64 k.
//   Blocks with blockIdx.y==0 additionally emit the c-partial for their
//   (j-tile, z) using the lin tile already staged in Bs (parallel, no serial
//   single-block tail).
// ---------------------------------------------------------------------------
__global__ __launch_bounds__(256) void kA(const float* __restrict__ V,
                                          const float* __restrict__ lin,
                                          const float* __restrict__ biasV) {
    __shared__ float As[64][68];   // [k-local][j'-local]
    __shared__ float Bs[64][68];   // [k-local][j-local]

    const int t  = threadIdx.x;
    const int tx = t & 15;         // j  micro coord
    const int ty = t >> 4;         // j' micro coord
    const int j0  = blockIdx.x * 64;
    const int jp0 = blockIdx.y * 64;
    const int z   = blockIdx.z;

    // As: for each of 8 i's, V[i, jp0:jp0+64, 0:8] is 512 CONTIGUOUS floats
    // (j' stride 8, h stride 1). k-local = i_local*8 + h.
    #pragma unroll
    for (int il = 0; il < 8; ++il) {
        const float* chunk = V + (z * 8 + il) * (Cc * Hh) + jp0 * Hh;
        float v0 = chunk[t];
        float v1 = chunk[t + 256];
        As[il * 8 + (t & 7)][t >> 3]        = v0;
        As[il * 8 + (t & 7)][(t >> 3) + 32] = v1;
    }
    // Bs: lin rows z*64 .. z*64+63, cols j0..j0+63
    #pragma unroll
    for (int it = 0; it < 4; ++it) {
        int r  = (t >> 4) + it * 16;
        int c4 = (t & 15) * 4;
        *(float4*)&Bs[r][c4] = *(const float4*)&lin[(z * 64 + r) * Cc + j0 + c4];
    }
    __syncthreads();

    float acc[4][4] = {};
    #pragma unroll 16
    for (int k = 0; k < 64; ++k) {
        float4 a4 = *(const float4*)&As[k][ty * 4];
        float4 b4 = *(const float4*)&Bs[k][tx * 4];
        float a[4] = {a4.x, a4.y, a4.z, a4.w};
        float b[4] = {b4.x, b4.y, b4.z, b4.w};
        #pragma unroll
        for (int e1 = 0; e1 < 4; ++e1)
            #pragma unroll
            for (int e2 = 0; e2 < 4; ++e2)
                acc[e1][e2] = fmaf(a[e1], b[e2], acc[e1][e2]);
    }

    #pragma unroll
    for (int e1 = 0; e1 < 4; ++e1) {
        int jp = jp0 + ty * 4 + e1;
        float4 val = make_float4(acc[e1][0], acc[e1][1], acc[e1][2], acc[e1][3]);
        *(float4*)&g_partial[(z * Cc + jp) * Cc + j0 + tx * 4] = val;
    }

    // c-partial: c_part[z][j0+jj] = sum_{k<64} biasV[z*64+k] * lin[z*64+k][j0+jj]
    // Bs still holds the lin tile (nothing wrote it after the sync).
    if (blockIdx.y == 0 && t < 64) {
        float s = 0.0f;
        #pragma unroll 8
        for (int k = 0; k < 64; ++k)
            s = fmaf(biasV[z * 64 + k], Bs[k][t], s);   // biasV read is a broadcast
        g_cp[z * Cc + j0 + t] = s;
    }
}

// ---------------------------------------------------------------------------
// Kernel R: reduce split-K partials into g_W; block 256 reduces c partials.
// ---------------------------------------------------------------------------
__global__ __launch_bounds__(256) void kR() {
    if (blockIdx.x < 256) {
        int idx = blockIdx.x * 256 + threadIdx.x;
        float s = 0.0f;
        #pragma unroll
        for (int z = 0; z < KSPLIT; ++z)
            s += g_partial[z * (Cc * Cc) + idx];
        g_W[idx] = s;
    } else {
        int j = threadIdx.x;
        float s = 0.0f;
        #pragma unroll
        for (int z = 0; z < KSPLIT; ++z)
            s += g_cp[z * Cc + j];
        g_c[j] = s;
    }
}

// ---------------------------------------------------------------------------
// Kernel B: out[m][j] = sum_{j'} v[m][j'] * W[j'][j] + c[j]
//   M = B*N = 4096, Nout = 256, K = 256.
//   Block: 64(m) x 64(j) tile, 256 threads, 4x4 micro. Grid (4, 64).
//   v staged TRANSPOSED: VsT[k][m] with stride 68 so the compute a-read
//   VsT[kk][ty*4] is ONE 16B-aligned LDS.128 broadcast (2 distinct addrs
//   per warp) -> 1 crossbar wavefront; b-read is the proven row float4.
// ---------------------------------------------------------------------------
__global__ __launch_bounds__(256) void kB(const float* __restrict__ v,
                                          float* __restrict__ out) {
    __shared__ float VsT[64][68]; // [k-local][m-local]
    __shared__ float Ws[64][68];  // [k-local][j-local]

    const int t  = threadIdx.x;
    const int tx = t & 15;        // j micro coord
    const int ty = t >> 4;        // m micro coord
    const int j0 = blockIdx.x * 64;
    const int m0 = blockIdx.y * 64;

    float acc[4][4] = {};

    for (int ks = 0; ks < Cc; ks += 64) {
        __syncthreads();  // previous chunk fully consumed
        // VsT: v rows m0..m0+63, k cols ks..ks+63, transposed at store.
        #pragma unroll
        for (int it = 0; it < 4; ++it) {
            int r  = (t >> 4) + it * 16;   // m row 0..63
            int c4 = (t & 15) * 4;         // k col 0..60
            float4 val = *(const float4*)&v[(m0 + r) * Cc + ks + c4];
            VsT[c4 + 0][r] = val.x;
            VsT[c4 + 1][r] = val.y;
            VsT[c4 + 2][r] = val.z;
            VsT[c4 + 3][r] = val.w;
        }
        #pragma unroll
        for (int it = 0; it < 4; ++it) {
            int r  = (t >> 4) + it * 16;   // k row
            int c4 = (t & 15) * 4;         // j col
            *(float4*)&Ws[r][c4] = *(const float4*)&g_W[(ks + r) * Cc + j0 + c4];
        }
        __syncthreads();

        #pragma unroll 16
        for (int kk = 0; kk < 64; ++kk) {
            float4 a4 = *(const float4*)&VsT[kk][ty * 4];   // aligned broadcast
            float4 b4 = *(const float4*)&Ws[kk][tx * 4];
            float a[4] = {a4.x, a4.y, a4.z, a4.w};
            float b[4] = {b4.x, b4.y, b4.z, b4.w};
            #pragma unroll
            for (int e1 = 0; e1 < 4; ++e1)
                #pragma unroll
                for (int e2 = 0; e2 < 4; ++e2)
                    acc[e1][e2] = fmaf(a[e1], b[e2], acc[e1][e2]);
        }
    }

    float4 cv = *(const float4*)&g_c[j0 + tx * 4];
    #pragma unroll
    for (int e1 = 0; e1 < 4; ++e1) {
        int m = m0 + ty * 4 + e1;
        float4 val = make_float4(acc[e1][0] + cv.x, acc[e1][1] + cv.y,
                                 acc[e1][2] + cv.z, acc[e1][3] + cv.w);
        *(float4*)&out[m * Cc + j0 + tx * 4] = val;
    }
}

// ---------------------------------------------------------------------------
// Inputs (metadata order): q, k, v, bias, atten_mask, Q, K, V,
//                          bias_Q, bias_K, bias_V, linear_output
// Only v (d_in[2]), V (d_in[7]), bias_V (d_in[10]), linear_output (d_in[11])
// matter: softmax over m sums to 1, so the attention block is the identity
// on vh; everything folds to out = v @ (Vr^T @ lin) + c.
// ---------------------------------------------------------------------------
extern "C" void kernel_launch(void* const* d_in, const int* in_sizes, int n_in,
                              void* d_out, int out_size) {
    const float* v     = (const float*)d_in[2];
    const float* V     = (const float*)d_in[7];
    const float* biasV = (const float*)d_in[10];
    const float* lin   = (const float*)d_in[11];
    float* out = (float*)d_out;

    kA<<<dim3(4, 4, KSPLIT), 256>>>(V, lin, biasV);
    kR<<<257, 256>>>();
    kB<<<dim3(4, 64), 256>>>(v, out);
}

// round 8
// speedup vs baseline: 3.0788x; 1.2106x over previous
#include <cuda_runtime.h>
#include <cuda_bf16.h>
#include <cstdint>

// Problem constants: B=4, N=1024, C=256, H=8
#define Cc 256
#define Hh 8
#define KSPLIT 32    // split-K factor for kernel A (deterministic, no atomics)

// Scratch (no allocation allowed -> __device__ globals)
__device__ float g_partial[KSPLIT * Cc * Cc];     // 8 MB split-K partials
__device__ float g_cp[KSPLIT * Cc];               // c partials per k-split
__device__ float g_c[Cc];                         // folded bias vector
__device__ __nv_bfloat16 g_Wt_hi[Cc * Cc];        // W^T hi split  [j][k]
__device__ __nv_bfloat16 g_Wt_lo[Cc * Cc];        // W^T lo split  [j][k]

// ---- warp-level bf16 HMMA (non-accelerated ISA, compiles for sm_103) ------
__device__ __forceinline__ void mma_bf16(float* c, const uint32_t* a,
                                         const uint32_t* b) {
    asm volatile(
        "mma.sync.aligned.m16n8k16.row.col.f32.bf16.bf16.f32 "
        "{%0,%1,%2,%3}, {%4,%5,%6,%7}, {%8,%9}, {%0,%1,%2,%3};"
        : "+f"(c[0]), "+f"(c[1]), "+f"(c[2]), "+f"(c[3])
        : "r"(a[0]), "r"(a[1]), "r"(a[2]), "r"(a[3]), "r"(b[0]), "r"(b[1]));
}

// ---------------------------------------------------------------------------
// Kernel A (unchanged, measured good): split-K fold partials + parallel
// c-partials from the already-staged lin tile.
// ---------------------------------------------------------------------------
__global__ __launch_bounds__(256) void kA(const float* __restrict__ V,
                                          const float* __restrict__ lin,
                                          const float* __restrict__ biasV) {
    __shared__ float As[64][68];
    __shared__ float Bs[64][68];

    const int t  = threadIdx.x;
    const int tx = t & 15;
    const int ty = t >> 4;
    const int j0  = blockIdx.x * 64;
    const int jp0 = blockIdx.y * 64;
    const int z   = blockIdx.z;

    #pragma unroll
    for (int il = 0; il < 8; ++il) {
        const float* chunk = V + (z * 8 + il) * (Cc * Hh) + jp0 * Hh;
        float v0 = chunk[t];
        float v1 = chunk[t + 256];
        As[il * 8 + (t & 7)][t >> 3]        = v0;
        As[il * 8 + (t & 7)][(t >> 3) + 32] = v1;
    }
    #pragma unroll
    for (int it = 0; it < 4; ++it) {
        int r  = (t >> 4) + it * 16;
        int c4 = (t & 15) * 4;
        *(float4*)&Bs[r][c4] = *(const float4*)&lin[(z * 64 + r) * Cc + j0 + c4];
    }
    __syncthreads();

    float acc[4][4] = {};
    #pragma unroll 16
    for (int k = 0; k < 64; ++k) {
        float4 a4 = *(const float4*)&As[k][ty * 4];
        float4 b4 = *(const float4*)&Bs[k][tx * 4];
        float a[4] = {a4.x, a4.y, a4.z, a4.w};
        float b[4] = {b4.x, b4.y, b4.z, b4.w};
        #pragma unroll
        for (int e1 = 0; e1 < 4; ++e1)
            #pragma unroll
            for (int e2 = 0; e2 < 4; ++e2)
                acc[e1][e2] = fmaf(a[e1], b[e2], acc[e1][e2]);
    }

    #pragma unroll
    for (int e1 = 0; e1 < 4; ++e1) {
        int jp = jp0 + ty * 4 + e1;
        *(float4*)&g_partial[(z * Cc + jp) * Cc + j0 + tx * 4] =
            make_float4(acc[e1][0], acc[e1][1], acc[e1][2], acc[e1][3]);
    }

    if (blockIdx.y == 0 && t < 64) {
        float s = 0.0f;
        #pragma unroll 8
        for (int k = 0; k < 64; ++k)
            s = fmaf(biasV[z * 64 + k], Bs[k][t], s);
        g_cp[z * Cc + j0 + t] = s;
    }
}

// ---------------------------------------------------------------------------
// Kernel R: reduce split-K partials -> transposed, bf16 hi/lo split W.
// Within a z-slab, flat idx = jp*256 + j; writes g_Wt_*[j][jp].
// Block 256 reduces the c partials.
// ---------------------------------------------------------------------------
__global__ __launch_bounds__(256) void kR() {
    if (blockIdx.x < 256) {
        int idx = blockIdx.x * 256 + threadIdx.x;
        float s = 0.0f;
        #pragma unroll
        for (int z = 0; z < KSPLIT; ++z)
            s += g_partial[z * (Cc * Cc) + idx];
        int jp = idx >> 8, j = idx & 255;
        __nv_bfloat16 hi = __float2bfloat16_rn(s);
        float lof = s - __bfloat162float(hi);
        g_Wt_hi[j * Cc + jp] = hi;
        g_Wt_lo[j * Cc + jp] = __float2bfloat16_rn(lof);
    } else {
        int j = threadIdx.x;
        float s = 0.0f;
        #pragma unroll
        for (int z = 0; z < KSPLIT; ++z)
            s += g_cp[z * Cc + j];
        g_c[j] = s;
    }
}

// ---------------------------------------------------------------------------
// Kernel B (HMMA): out[m][j] = sum_k v[m,k] * W[k,j] + c[j]
//   CTA: 64m x 64j, 256 threads (8 warps). Grid (4 j-tiles, 64 m-tiles).
//   Warp w: m-tile mw=w&3 (16 rows), n-half nh=w>>2 (32 cols = 4 n8-tiles).
//   K in 4 chunks of 64, staged in smem as u32(bf16x2) rows, stride 36 u32
//   (36 mod 32 = 4 -> fragment loads 4*row+klane hit 32 distinct banks).
//   bf16 split: D = Ah*Bh + Ah*Bl + Al*Bh, fp32 accumulate.
// ---------------------------------------------------------------------------
__global__ __launch_bounds__(256) void kB_mma(const float* __restrict__ v,
                                              float* __restrict__ out) {
    __shared__ uint32_t Ah[64][36], Al[64][36];   // [m][k-pair]
    __shared__ uint32_t Bh[64][36], Bl[64][36];   // [j][k-pair]

    const int t    = threadIdx.x;
    const int w    = t >> 5;
    const int lane = t & 31;
    const int mw   = (w & 3) * 16;
    const int nh   = (w >> 2) * 32;
    const int j0 = blockIdx.x * 64;
    const int m0 = blockIdx.y * 64;

    float acc[4][4] = {};   // [n8-tile][frag]

    for (int kc = 0; kc < Cc; kc += 64) {
        __syncthreads();
        // ---- stage A: convert v[m0+0..63][kc+0..63] fp32 -> bf16 hi/lo ----
        #pragma unroll
        for (int it = 0; it < 4; ++it) {
            int item = t + it * 256;            // 0..1023
            int m = item >> 4, g = item & 15;   // 16 float4-groups per row
            float4 x = *(const float4*)&v[(m0 + m) * Cc + kc + g * 4];
            __nv_bfloat162 h0 = __floats2bfloat162_rn(x.x, x.y);
            __nv_bfloat162 h1 = __floats2bfloat162_rn(x.z, x.w);
            __nv_bfloat162 l0 = __floats2bfloat162_rn(x.x - __bfloat162float(h0.x),
                                                      x.y - __bfloat162float(h0.y));
            __nv_bfloat162 l1 = __floats2bfloat162_rn(x.z - __bfloat162float(h1.x),
                                                      x.w - __bfloat162float(h1.y));
            Ah[m][g * 2]     = *(uint32_t*)&h0;
            Ah[m][g * 2 + 1] = *(uint32_t*)&h1;
            Al[m][g * 2]     = *(uint32_t*)&l0;
            Al[m][g * 2 + 1] = *(uint32_t*)&l1;
        }
        // ---- stage B: copy pre-split g_Wt rows (k-contiguous) -------------
        #pragma unroll
        for (int it = 0; it < 4; ++it) {
            int item = t + it * 256;            // 0..1023 u64 units
            int j = item >> 4, g = item & 15;   // 16 u64 per 64-k row
            *(uint64_t*)&Bh[j][g * 2] =
                *(const uint64_t*)&g_Wt_hi[(j0 + j) * Cc + kc + g * 4];
            *(uint64_t*)&Bl[j][g * 2] =
                *(const uint64_t*)&g_Wt_lo[(j0 + j) * Cc + kc + g * 4];
        }
        __syncthreads();

        #pragma unroll
        for (int ks = 0; ks < 4; ++ks) {
            const int row = mw + (lane >> 2);
            const int kk  = ks * 8 + (lane & 3);
            uint32_t ah[4], al[4];
            ah[0] = Ah[row][kk];     ah[1] = Ah[row + 8][kk];
            ah[2] = Ah[row][kk + 4]; ah[3] = Ah[row + 8][kk + 4];
            al[0] = Al[row][kk];     al[1] = Al[row + 8][kk];
            al[2] = Al[row][kk + 4]; al[3] = Al[row + 8][kk + 4];
            #pragma unroll
            for (int nt = 0; nt < 4; ++nt) {
                const int j = nh + nt * 8 + (lane >> 2);
                uint32_t bh[2], bl[2];
                bh[0] = Bh[j][kk]; bh[1] = Bh[j][kk + 4];
                bl[0] = Bl[j][kk]; bl[1] = Bl[j][kk + 4];
                mma_bf16(acc[nt], ah, bh);
                mma_bf16(acc[nt], ah, bl);
                mma_bf16(acc[nt], al, bh);
            }
        }
    }

    // ---- epilogue: D frag (c0,c1)=(row, col/col+1), (c2,c3)=row+8 ---------
    const int mrow = m0 + mw + (lane >> 2);
    #pragma unroll
    for (int nt = 0; nt < 4; ++nt) {
        const int j = j0 + nh + nt * 8 + (lane & 3) * 2;
        float2 cj = *(const float2*)&g_c[j];
        *(float2*)&out[mrow * Cc + j] =
            make_float2(acc[nt][0] + cj.x, acc[nt][1] + cj.y);
        *(float2*)&out[(mrow + 8) * Cc + j] =
            make_float2(acc[nt][2] + cj.x, acc[nt][3] + cj.y);
    }
}

// ---------------------------------------------------------------------------
// Inputs (metadata order): q, k, v, bias, atten_mask, Q, K, V,
//                          bias_Q, bias_K, bias_V, linear_output
// softmax over m sums to 1 -> attention is identity on vh; everything folds
// to out = v @ (Vr^T @ lin) + c.
// ---------------------------------------------------------------------------
extern "C" void kernel_launch(void* const* d_in, const int* in_sizes, int n_in,
                              void* d_out, int out_size) {
    const float* v     = (const float*)d_in[2];
    const float* V     = (const float*)d_in[7];
    const float* biasV = (const float*)d_in[10];
    const float* lin   = (const float*)d_in[11];
    float* out = (float*)d_out;

    kA<<<dim3(4, 4, KSPLIT), 256>>>(V, lin, biasV);
    kR<<<257, 256>>>();
    kB_mma<<<dim3(4, 64), 256>>>(v, out);
}

// round 9
// speedup vs baseline: 3.2296x; 1.0490x over previous
#include <cuda_runtime.h>
#include <cuda_bf16.h>
#include <cstdint>

// Problem constants: B=4, N=1024, C=256, H=8
#define Cc 256
#define Hh 8
#define ZA 8         // split-K factor for kernel A (deterministic, no atomics)

// Scratch (no allocation allowed -> __device__ globals)
__device__ float g_partial[ZA * Cc * Cc];         // 2 MB split-K partials
__device__ float g_cp[ZA * Cc];                   // c partials per k-split
__device__ float g_c[Cc];                         // folded bias vector
__device__ __nv_bfloat16 g_Wt_hi[Cc * Cc];        // W^T hi split  [j][k]
__device__ __nv_bfloat16 g_Wt_lo[Cc * Cc];        // W^T lo split  [j][k]

// ---- warp-level bf16 HMMA (non-accelerated ISA, compiles for sm_103) ------
__device__ __forceinline__ void mma_bf16(float* c, const uint32_t* a,
                                         const uint32_t* b) {
    asm volatile(
        "mma.sync.aligned.m16n8k16.row.col.f32.bf16.bf16.f32 "
        "{%0,%1,%2,%3}, {%4,%5,%6,%7}, {%8,%9}, {%0,%1,%2,%3};"
        : "+f"(c[0]), "+f"(c[1]), "+f"(c[2]), "+f"(c[3])
        : "r"(a[0]), "r"(a[1]), "r"(a[2]), "r"(a[3]), "r"(b[0]), "r"(b[1]));
}
__device__ __forceinline__ uint32_t bf2(float x, float y) {
    __nv_bfloat162 h = __floats2bfloat162_rn(x, y);
    return *(uint32_t*)&h;
}
__device__ __forceinline__ float2 unbf2(uint32_t u) {
    __nv_bfloat162 h = *(__nv_bfloat162*)&u;
    return make_float2(__bfloat162float(h.x), __bfloat162float(h.y));
}

// ---------------------------------------------------------------------------
// Kernel A (HMMA): partial_z[j'][j] = sum_{k in z-chunk} Vr[k][j'] * lin[k][j]
//   Vr[k=i*8+h][j'] = V[i*2048 + j'*8 + h]. CTA: 64(j') x 64(j), K=256.
//   Grid (4 j, 4 j', ZA). bf16 split: Ah*Bh + Ah*Bl + Al*Bh, fp32 acc.
//   Warp w: rows mw=(w&3)*16, cols nh=(w>>2)*32. Stride-36 smem rows ->
//   fragment loads (4*row + klane) % 32 cover 32 banks, conflict-free.
//   y==0 blocks also accumulate c-partials from the staged lin tile.
// ---------------------------------------------------------------------------
__global__ __launch_bounds__(256) void kA_mma(const float* __restrict__ V,
                                              const float* __restrict__ lin,
                                              const float* __restrict__ biasV) {
    __shared__ uint32_t Ah[64][36], Al[64][36];   // [j'][k-pair]
    __shared__ uint32_t Bh[64][36], Bl[64][36];   // [j][k-pair]

    const int t    = threadIdx.x;
    const int w    = t >> 5;
    const int lane = t & 31;
    const int mw   = (w & 3) * 16;
    const int nh   = (w >> 2) * 32;
    const int j0  = blockIdx.x * 64;
    const int jp0 = blockIdx.y * 64;
    const int z   = blockIdx.z;

    float acc[4][4] = {};
    float csum = 0.0f;

    for (int kc = 0; kc < 4; ++kc) {              // 4 chunks of 64 k
        const int i0 = z * 32 + kc * 8;           // 8 i's per chunk
        const int k0 = z * 256 + kc * 64;
        __syncthreads();
        // ---- stage A: (j', i) items; 8 contiguous floats each ------------
        #pragma unroll
        for (int q = 0; q < 2; ++q) {
            int item = t + q * 256;               // 0..511
            int jp = item & 63, il = item >> 6;   // il 0..7
            const float* src = V + (i0 + il) * (Cc * Hh) + (jp0 + jp) * Hh;
            float4 a = *(const float4*)src;
            float4 b = *(const float4*)(src + 4);
            uint32_t h0 = bf2(a.x, a.y), h1 = bf2(a.z, a.w);
            uint32_t h2 = bf2(b.x, b.y), h3 = bf2(b.z, b.w);
            float2 f0 = unbf2(h0), f1 = unbf2(h1), f2 = unbf2(h2), f3 = unbf2(h3);
            Ah[jp][il * 4 + 0] = h0;
            Ah[jp][il * 4 + 1] = h1;
            Ah[jp][il * 4 + 2] = h2;
            Ah[jp][il * 4 + 3] = h3;
            Al[jp][il * 4 + 0] = bf2(a.x - f0.x, a.y - f0.y);
            Al[jp][il * 4 + 1] = bf2(a.z - f1.x, a.w - f1.y);
            Al[jp][il * 4 + 2] = bf2(b.x - f2.x, b.y - f2.y);
            Al[jp][il * 4 + 3] = bf2(b.z - f3.x, b.w - f3.y);
        }
        // ---- stage B: transpose lin chunk; coalesced loads across j ------
        #pragma unroll
        for (int it = 0; it < 8; ++it) {
            int item = t + it * 256;              // 0..2047
            int j = item & 63, kp = item >> 6;    // kp 0..31
            float x0 = lin[(k0 + kp * 2) * Cc + j0 + j];
            float x1 = lin[(k0 + kp * 2 + 1) * Cc + j0 + j];
            uint32_t h = bf2(x0, x1);
            float2 f = unbf2(h);
            Bh[j][kp] = h;
            Bl[j][kp] = bf2(x0 - f.x, x1 - f.y);
        }
        __syncthreads();

        #pragma unroll
        for (int ks = 0; ks < 4; ++ks) {
            const int row = mw + (lane >> 2);
            const int kk  = ks * 8 + (lane & 3);
            uint32_t ah[4], al[4];
            ah[0] = Ah[row][kk];     ah[1] = Ah[row + 8][kk];
            ah[2] = Ah[row][kk + 4]; ah[3] = Ah[row + 8][kk + 4];
            al[0] = Al[row][kk];     al[1] = Al[row + 8][kk];
            al[2] = Al[row][kk + 4]; al[3] = Al[row + 8][kk + 4];
            #pragma unroll
            for (int nt = 0; nt < 4; ++nt) {
                const int j = nh + nt * 8 + (lane >> 2);
                uint32_t bh[2], bl[2];
                bh[0] = Bh[j][kk]; bh[1] = Bh[j][kk + 4];
                bl[0] = Bl[j][kk]; bl[1] = Bl[j][kk + 4];
                mma_bf16(acc[nt], ah, bh);
                mma_bf16(acc[nt], ah, bl);
                mma_bf16(acc[nt], al, bh);
            }
        }

        // ---- c-partial from staged bf16 lin tile (y==0 blocks only) ------
        if (blockIdx.y == 0 && t < 64) {
            #pragma unroll 8
            for (int kp = 0; kp < 32; ++kp) {
                float2 bv = *(const float2*)&biasV[k0 + kp * 2];
                float2 hh = unbf2(Bh[t][kp]);
                float2 ll = unbf2(Bl[t][kp]);
                csum = fmaf(bv.x, hh.x + ll.x, csum);
                csum = fmaf(bv.y, hh.y + ll.y, csum);
            }
        }
    }

    // epilogue: fp32 partials
    const int jr = jp0 + mw + (lane >> 2);
    #pragma unroll
    for (int nt = 0; nt < 4; ++nt) {
        const int j = j0 + nh + nt * 8 + (lane & 3) * 2;
        *(float2*)&g_partial[z * (Cc * Cc) + jr * Cc + j] =
            make_float2(acc[nt][0], acc[nt][1]);
        *(float2*)&g_partial[z * (Cc * Cc) + (jr + 8) * Cc + j] =
            make_float2(acc[nt][2], acc[nt][3]);
    }
    if (blockIdx.y == 0 && t < 64)
        g_cp[z * Cc + j0 + t] = csum;
}

// ---------------------------------------------------------------------------
// Kernel R: reduce split-K partials -> transposed, bf16 hi/lo split W.
// Within a z-slab, flat idx = jp*256 + j; writes g_Wt_*[j][jp].
// Block 256 reduces the c partials.
// ---------------------------------------------------------------------------
__global__ __launch_bounds__(256) void kR() {
    if (blockIdx.x < 256) {
        int idx = blockIdx.x * 256 + threadIdx.x;
        float s = 0.0f;
        #pragma unroll
        for (int z = 0; z < ZA; ++z)
            s += g_partial[z * (Cc * Cc) + idx];
        int jp = idx >> 8, j = idx & 255;
        __nv_bfloat16 hi = __float2bfloat16_rn(s);
        float lof = s - __bfloat162float(hi);
        g_Wt_hi[j * Cc + jp] = hi;
        g_Wt_lo[j * Cc + jp] = __float2bfloat16_rn(lof);
    } else {
        int j = threadIdx.x;
        float s = 0.0f;
        #pragma unroll
        for (int z = 0; z < ZA; ++z)
            s += g_cp[z * Cc + j];
        g_c[j] = s;
    }
}

// ---------------------------------------------------------------------------
// Kernel B (HMMA, unchanged from measured-good R8): out = v @ W + c
// ---------------------------------------------------------------------------
__global__ __launch_bounds__(256) void kB_mma(const float* __restrict__ v,
                                              float* __restrict__ out) {
    __shared__ uint32_t Ah[64][36], Al[64][36];   // [m][k-pair]
    __shared__ uint32_t Bh[64][36], Bl[64][36];   // [j][k-pair]

    const int t    = threadIdx.x;
    const int w    = t >> 5;
    const int lane = t & 31;
    const int mw   = (w & 3) * 16;
    const int nh   = (w >> 2) * 32;
    const int j0 = blockIdx.x * 64;
    const int m0 = blockIdx.y * 64;

    float acc[4][4] = {};

    for (int kc = 0; kc < Cc; kc += 64) {
        __syncthreads();
        #pragma unroll
        for (int it = 0; it < 4; ++it) {
            int item = t + it * 256;
            int m = item >> 4, g = item & 15;
            float4 x = *(const float4*)&v[(m0 + m) * Cc + kc + g * 4];
            uint32_t h0 = bf2(x.x, x.y), h1 = bf2(x.z, x.w);
            float2 f0 = unbf2(h0), f1 = unbf2(h1);
            Ah[m][g * 2]     = h0;
            Ah[m][g * 2 + 1] = h1;
            Al[m][g * 2]     = bf2(x.x - f0.x, x.y - f0.y);
            Al[m][g * 2 + 1] = bf2(x.z - f1.x, x.w - f1.y);
        }
        #pragma unroll
        for (int it = 0; it < 4; ++it) {
            int item = t + it * 256;
            int j = item >> 4, g = item & 15;
            *(uint64_t*)&Bh[j][g * 2] =
                *(const uint64_t*)&g_Wt_hi[(j0 + j) * Cc + kc + g * 4];
            *(uint64_t*)&Bl[j][g * 2] =
                *(const uint64_t*)&g_Wt_lo[(j0 + j) * Cc + kc + g * 4];
        }
        __syncthreads();

        #pragma unroll
        for (int ks = 0; ks < 4; ++ks) {
            const int row = mw + (lane >> 2);
            const int kk  = ks * 8 + (lane & 3);
            uint32_t ah[4], al[4];
            ah[0] = Ah[row][kk];     ah[1] = Ah[row + 8][kk];
            ah[2] = Ah[row][kk + 4]; ah[3] = Ah[row + 8][kk + 4];
            al[0] = Al[row][kk];     al[1] = Al[row + 8][kk];
            al[2] = Al[row][kk + 4]; al[3] = Al[row + 8][kk + 4];
            #pragma unroll
            for (int nt = 0; nt < 4; ++nt) {
                const int j = nh + nt * 8 + (lane >> 2);
                uint32_t bh[2], bl[2];
                bh[0] = Bh[j][kk]; bh[1] = Bh[j][kk + 4];
                bl[0] = Bl[j][kk]; bl[1] = Bl[j][kk + 4];
                mma_bf16(acc[nt], ah, bh);
                mma_bf16(acc[nt], ah, bl);
                mma_bf16(acc[nt], al, bh);
            }
        }
    }

    const int mrow = m0 + mw + (lane >> 2);
    #pragma unroll
    for (int nt = 0; nt < 4; ++nt) {
        const int j = j0 + nh + nt * 8 + (lane & 3) * 2;
        float2 cj = *(const float2*)&g_c[j];
        *(float2*)&out[mrow * Cc + j] =
            make_float2(acc[nt][0] + cj.x, acc[nt][1] + cj.y);
        *(float2*)&out[(mrow + 8) * Cc + j] =
            make_float2(acc[nt][2] + cj.x, acc[nt][3] + cj.y);
    }
}

// ---------------------------------------------------------------------------
// Inputs (metadata order): q, k, v, bias, atten_mask, Q, K, V,
//                          bias_Q, bias_K, bias_V, linear_output
// softmax over m sums to 1 -> attention is identity on vh; everything folds
// to out = v @ (Vr^T @ lin) + c.
// ---------------------------------------------------------------------------
extern "C" void kernel_launch(void* const* d_in, const int* in_sizes, int n_in,
                              void* d_out, int out_size) {
    const float* v     = (const float*)d_in[2];
    const float* V     = (const float*)d_in[7];
    const float* biasV = (const float*)d_in[10];
    const float* lin   = (const float*)d_in[11];
    float* out = (float*)d_out;

    kA_mma<<<dim3(4, 4, ZA), 256>>>(V, lin, biasV);
    kR<<<257, 256>>>();
    kB_mma<<<dim3(4, 64), 256>>>(v, out);
}

// round 10
// speedup vs baseline: 3.8495x; 1.1920x over previous
#include <cuda_runtime.h>
#include <cuda_bf16.h>
#include <cstdint>

// Problem constants: B=4, N=1024, C=256, H=8
#define Cc 256
#define Hh 8
#define ZA 16        // split-K factor for kernel A (deterministic, no atomics)

// Scratch (no allocation allowed -> __device__ globals)
__device__ float g_partial[ZA * Cc * Cc];         // 4 MB split-K partials
__device__ float g_cp[ZA * Cc];                   // c partials per k-split
__device__ float g_c[Cc];                         // folded bias vector
__device__ __nv_bfloat16 g_Wt_hi[Cc * Cc];        // W^T hi split  [j][k]
__device__ __nv_bfloat16 g_Wt_lo[Cc * Cc];        // W^T lo split  [j][k]

// ---- warp-level bf16 HMMA (non-accelerated ISA, compiles for sm_103) ------
__device__ __forceinline__ void mma_bf16(float* c, const uint32_t* a,
                                         const uint32_t* b) {
    asm volatile(
        "mma.sync.aligned.m16n8k16.row.col.f32.bf16.bf16.f32 "
        "{%0,%1,%2,%3}, {%4,%5,%6,%7}, {%8,%9}, {%0,%1,%2,%3};"
        : "+f"(c[0]), "+f"(c[1]), "+f"(c[2]), "+f"(c[3])
        : "r"(a[0]), "r"(a[1]), "r"(a[2]), "r"(a[3]), "r"(b[0]), "r"(b[1]));
}
__device__ __forceinline__ uint32_t bf2(float x, float y) {
    __nv_bfloat162 h = __floats2bfloat162_rn(x, y);
    return *(uint32_t*)&h;
}
__device__ __forceinline__ float2 unbf2(uint32_t u) {
    __nv_bfloat162 h = *(__nv_bfloat162*)&u;
    return make_float2(__bfloat162float(h.x), __bfloat162float(h.y));
}

// ---------------------------------------------------------------------------
// Kernel A (HMMA, pipelined): partial_z[j'][j] = sum_k Vr[k][j'] * lin[k][j]
//   Vr[k=i*8+h][j'] = V[i*2048 + j'*8 + h]. CTA: 64(j') x 64(j), K=128 (2
//   chunks of 64). Grid (4 j, 4 j', ZA=16) = 256 CTAs -> 2/SM.
//   Pipeline: chunk n+1's global loads issue in registers while chunk n's
//   MMAs consume smem. bf16 split: Ah*Bh + Ah*Bl + Al*Bh, fp32 acc.
// ---------------------------------------------------------------------------
__global__ __launch_bounds__(256) void kA_mma(const float* __restrict__ V,
                                              const float* __restrict__ lin,
                                              const float* __restrict__ biasV) {
    __shared__ uint32_t Ah[64][36], Al[64][36];   // [j'][k-pair]
    __shared__ uint32_t Bh[64][36], Bl[64][36];   // [j][k-pair]

    const int t    = threadIdx.x;
    const int w    = t >> 5;
    const int lane = t & 31;
    const int mw   = (w & 3) * 16;
    const int nh   = (w >> 2) * 32;
    const int j0  = blockIdx.x * 64;
    const int jp0 = blockIdx.y * 64;
    const int z   = blockIdx.z;

    float acc[4][4] = {};
    float csum = 0.0f;

    float4 pa[2][2];     // A prefetch: 2 items x 8 floats
    float  pb[8][2];     // B prefetch: 8 items x 2 floats

    // ---- prefetch chunk kc into registers ---------------------------------
    auto prefetch = [&](int kc) {
        const int i0 = z * 16 + kc * 8;
        const int k0 = z * 128 + kc * 64;
        #pragma unroll
        for (int q = 0; q < 2; ++q) {
            int item = t + q * 256;               // 0..511
            int jp = item & 63, il = item >> 6;
            const float* src = V + (i0 + il) * (Cc * Hh) + (jp0 + jp) * Hh;
            pa[q][0] = *(const float4*)src;
            pa[q][1] = *(const float4*)(src + 4);
        }
        #pragma unroll
        for (int it = 0; it < 8; ++it) {
            int item = t + it * 256;              // 0..2047
            int j = item & 63, kp = item >> 6;
            pb[it][0] = lin[(k0 + kp * 2) * Cc + j0 + j];
            pb[it][1] = lin[(k0 + kp * 2 + 1) * Cc + j0 + j];
        }
    };
    // ---- convert prefetched registers and store to smem -------------------
    auto store_smem = [&]() {
        #pragma unroll
        for (int q = 0; q < 2; ++q) {
            int item = t + q * 256;
            int jp = item & 63, il = item >> 6;
            float4 a = pa[q][0], b = pa[q][1];
            uint32_t h0 = bf2(a.x, a.y), h1 = bf2(a.z, a.w);
            uint32_t h2 = bf2(b.x, b.y), h3 = bf2(b.z, b.w);
            float2 f0 = unbf2(h0), f1 = unbf2(h1), f2 = unbf2(h2), f3 = unbf2(h3);
            Ah[jp][il * 4 + 0] = h0;
            Ah[jp][il * 4 + 1] = h1;
            Ah[jp][il * 4 + 2] = h2;
            Ah[jp][il * 4 + 3] = h3;
            Al[jp][il * 4 + 0] = bf2(a.x - f0.x, a.y - f0.y);
            Al[jp][il * 4 + 1] = bf2(a.z - f1.x, a.w - f1.y);
            Al[jp][il * 4 + 2] = bf2(b.x - f2.x, b.y - f2.y);
            Al[jp][il * 4 + 3] = bf2(b.z - f3.x, b.w - f3.y);
        }
        #pragma unroll
        for (int it = 0; it < 8; ++it) {
            int item = t + it * 256;
            int j = item & 63, kp = item >> 6;
            uint32_t h = bf2(pb[it][0], pb[it][1]);
            float2 f = unbf2(h);
            Bh[j][kp] = h;
            Bl[j][kp] = bf2(pb[it][0] - f.x, pb[it][1] - f.y);
        }
    };

    prefetch(0);
    #pragma unroll
    for (int kc = 0; kc < 2; ++kc) {
        __syncthreads();          // smem free from previous chunk's MMA
        store_smem();
        __syncthreads();
        if (kc == 0) prefetch(1); // overlap next loads with this chunk's MMA

        #pragma unroll
        for (int ks = 0; ks < 4; ++ks) {
            const int row = mw + (lane >> 2);
            const int kk  = ks * 8 + (lane & 3);
            uint32_t ah[4], al[4];
            ah[0] = Ah[row][kk];     ah[1] = Ah[row + 8][kk];
            ah[2] = Ah[row][kk + 4]; ah[3] = Ah[row + 8][kk + 4];
            al[0] = Al[row][kk];     al[1] = Al[row + 8][kk];
            al[2] = Al[row][kk + 4]; al[3] = Al[row + 8][kk + 4];
            #pragma unroll
            for (int nt = 0; nt < 4; ++nt) {
                const int j = nh + nt * 8 + (lane >> 2);
                uint32_t bh[2], bl[2];
                bh[0] = Bh[j][kk]; bh[1] = Bh[j][kk + 4];
                bl[0] = Bl[j][kk]; bl[1] = Bl[j][kk + 4];
                mma_bf16(acc[nt], ah, bh);
                mma_bf16(acc[nt], ah, bl);
                mma_bf16(acc[nt], al, bh);
            }
        }

        // c-partial from staged bf16 lin tile (y==0 blocks only)
        if (blockIdx.y == 0 && t < 64) {
            const int k0 = z * 128 + kc * 64;
            #pragma unroll 8
            for (int kp = 0; kp < 32; ++kp) {
                float2 bv = *(const float2*)&biasV[k0 + kp * 2];
                float2 hh = unbf2(Bh[t][kp]);
                float2 ll = unbf2(Bl[t][kp]);
                csum = fmaf(bv.x, hh.x + ll.x, csum);
                csum = fmaf(bv.y, hh.y + ll.y, csum);
            }
        }
    }

    const int jr = jp0 + mw + (lane >> 2);
    #pragma unroll
    for (int nt = 0; nt < 4; ++nt) {
        const int j = j0 + nh + nt * 8 + (lane & 3) * 2;
        *(float2*)&g_partial[z * (Cc * Cc) + jr * Cc + j] =
            make_float2(acc[nt][0], acc[nt][1]);
        *(float2*)&g_partial[z * (Cc * Cc) + (jr + 8) * Cc + j] =
            make_float2(acc[nt][2], acc[nt][3]);
    }
    if (blockIdx.y == 0 && t < 64)
        g_cp[z * Cc + j0 + t] = csum;
}

// ---------------------------------------------------------------------------
// Kernel R: reduce split-K partials -> transposed, bf16 hi/lo split W.
// Within a z-slab, flat idx = jp*256 + j; writes g_Wt_*[j][jp].
// Block 256 reduces the c partials.
// ---------------------------------------------------------------------------
__global__ __launch_bounds__(256) void kR() {
    if (blockIdx.x < 256) {
        int idx = blockIdx.x * 256 + threadIdx.x;
        float s = 0.0f;
        #pragma unroll
        for (int z = 0; z < ZA; ++z)
            s += g_partial[z * (Cc * Cc) + idx];
        int jp = idx >> 8, j = idx & 255;
        __nv_bfloat16 hi = __float2bfloat16_rn(s);
        float lof = s - __bfloat162float(hi);
        g_Wt_hi[j * Cc + jp] = hi;
        g_Wt_lo[j * Cc + jp] = __float2bfloat16_rn(lof);
    } else {
        int j = threadIdx.x;
        float s = 0.0f;
        #pragma unroll
        for (int z = 0; z < ZA; ++z)
            s += g_cp[z * Cc + j];
        g_c[j] = s;
    }
}

// ---------------------------------------------------------------------------
// Kernel B (HMMA, pipelined): out[m][j] = sum_k v[m,k] * W[k,j] + c[j]
//   CTA 64m x 64j, 4 K-chunks of 64, register-prefetch pipeline.
// ---------------------------------------------------------------------------
__global__ __launch_bounds__(256) void kB_mma(const float* __restrict__ v,
                                              float* __restrict__ out) {
    __shared__ uint32_t Ah[64][36], Al[64][36];   // [m][k-pair]
    __shared__ uint32_t Bh[64][36], Bl[64][36];   // [j][k-pair]

    const int t    = threadIdx.x;
    const int w    = t >> 5;
    const int lane = t & 31;
    const int mw   = (w & 3) * 16;
    const int nh   = (w >> 2) * 32;
    const int j0 = blockIdx.x * 64;
    const int m0 = blockIdx.y * 64;

    float acc[4][4] = {};

    float4   pa[4];        // A prefetch: 4 items x 4 floats
    uint64_t pbh[4], pbl[4];

    auto prefetch = [&](int kc) {
        #pragma unroll
        for (int it = 0; it < 4; ++it) {
            int item = t + it * 256;
            int m = item >> 4, g = item & 15;
            pa[it] = *(const float4*)&v[(m0 + m) * Cc + kc + g * 4];
            int j2 = item >> 4, g2 = item & 15;
            pbh[it] = *(const uint64_t*)&g_Wt_hi[(j0 + j2) * Cc + kc + g2 * 4];
            pbl[it] = *(const uint64_t*)&g_Wt_lo[(j0 + j2) * Cc + kc + g2 * 4];
        }
    };
    auto store_smem = [&]() {
        #pragma unroll
        for (int it = 0; it < 4; ++it) {
            int item = t + it * 256;
            int m = item >> 4, g = item & 15;
            float4 x = pa[it];
            uint32_t h0 = bf2(x.x, x.y), h1 = bf2(x.z, x.w);
            float2 f0 = unbf2(h0), f1 = unbf2(h1);
            Ah[m][g * 2]     = h0;
            Ah[m][g * 2 + 1] = h1;
            Al[m][g * 2]     = bf2(x.x - f0.x, x.y - f0.y);
            Al[m][g * 2 + 1] = bf2(x.z - f1.x, x.w - f1.y);
            *(uint64_t*)&Bh[m][g * 2] = pbh[it];
            *(uint64_t*)&Bl[m][g * 2] = pbl[it];
        }
    };

    prefetch(0);
    #pragma unroll
    for (int kc = 0; kc < 4; ++kc) {
        __syncthreads();
        store_smem();
        __syncthreads();
        if (kc < 3) prefetch((kc + 1) * 64);

        #pragma unroll
        for (int ks = 0; ks < 4; ++ks) {
            const int row = mw + (lane >> 2);
            const int kk  = ks * 8 + (lane & 3);
            uint32_t ah[4], al[4];
            ah[0] = Ah[row][kk];     ah[1] = Ah[row + 8][kk];
            ah[2] = Ah[row][kk + 4]; ah[3] = Ah[row + 8][kk + 4];
            al[0] = Al[row][kk];     al[1] = Al[row + 8][kk];
            al[2] = Al[row][kk + 4]; al[3] = Al[row + 8][kk + 4];
            #pragma unroll
            for (int nt = 0; nt < 4; ++nt) {
                const int j = nh + nt * 8 + (lane >> 2);
                uint32_t bh[2], bl[2];
                bh[0] = Bh[j][kk]; bh[1] = Bh[j][kk + 4];
                bl[0] = Bl[j][kk]; bl[1] = Bl[j][kk + 4];
                mma_bf16(acc[nt], ah, bh);
                mma_bf16(acc[nt], ah, bl);
                mma_bf16(acc[nt], al, bh);
            }
        }
    }

    const int mrow = m0 + mw + (lane >> 2);
    #pragma unroll
    for (int nt = 0; nt < 4; ++nt) {
        const int j = j0 + nh + nt * 8 + (lane & 3) * 2;
        float2 cj = *(const float2*)&g_c[j];
        *(float2*)&out[mrow * Cc + j] =
            make_float2(acc[nt][0] + cj.x, acc[nt][1] + cj.y);
        *(float2*)&out[(mrow + 8) * Cc + j] =
            make_float2(acc[nt][2] + cj.x, acc[nt][3] + cj.y);
    }
}

// ---------------------------------------------------------------------------
// Inputs (metadata order): q, k, v, bias, atten_mask, Q, K, V,
//                          bias_Q, bias_K, bias_V, linear_output
// softmax over m sums to 1 -> attention is identity on vh; everything folds
// to out = v @ (Vr^T @ lin) + c.
// ---------------------------------------------------------------------------
extern "C" void kernel_launch(void* const* d_in, const int* in_sizes, int n_in,
                              void* d_out, int out_size) {
    const float* v     = (const float*)d_in[2];
    const float* V     = (const float*)d_in[7];
    const float* biasV = (const float*)d_in[10];
    const float* lin   = (const float*)d_in[11];
    float* out = (float*)d_out;

    kA_mma<<<dim3(4, 4, ZA), 256>>>(V, lin, biasV);
    kR<<<257, 256>>>();
    kB_mma<<<dim3(4, 64), 256>>>(v, out);
}